// round 15
// baseline (speedup 1.0000x reference)
#include <cuda_runtime.h>
#include <cuda_fp16.h>
#include <math.h>
#include <cstdint>

// ---------------- problem constants ----------------
#define BQ   4096
#define NU   100000
#define DIM  128
#define TOPK 5
#define K1   6
#define TM   256                       // queries per CTA
#define TN   128                       // users per tile
#define QB   (BQ / TM)                 // 16
#define NCHUNK 9                       // user-range chunks -> 144 CTAs
#define NT_FLAT 782                    // ceil(100000/128); last tile: 32 valid + 96 pad
#define PADROWS 96
#define CAND 8
#define NCAND (NCHUNK * CAND)          // 72
#define SP_U32 65                      // half2-spill pitch in u32
#define NEG_INF (-3.402823466e38f)

typedef unsigned char uchar;

// ---------------- device scratch -------------------------------------------
__device__ float    g_ue_n[(size_t)NU * DIM];
__device__ float    g_q_n[(size_t)BQ * DIM];
__device__ uint32_t g_ubsw[(size_t)NT_FLAT * 8192];   // flat pre-swizzled f16 tiles (32KB each)
__device__ __half   g_qh[(size_t)BQ * DIM];
__device__ int      g_ci[(size_t)BQ * NCAND];

// ---------------- helpers ---------------------------------------------------
static __device__ __forceinline__ uint32_t smem_u32(const void* p) {
    uint32_t a;
    asm("{ .reg .u64 t; cvta.to.shared.u64 t, %1; cvt.u32.u64 %0, t; }" : "=r"(a) : "l"(p));
    return a;
}
static __device__ __forceinline__ void ldsm_x4(uint32_t addr, uint32_t r[4]) {
    asm volatile("ldmatrix.sync.aligned.m8n8.x4.shared.b16 {%0,%1,%2,%3}, [%4];"
                 : "=r"(r[0]), "=r"(r[1]), "=r"(r[2]), "=r"(r[3]) : "r"(addr));
}
static __device__ __forceinline__ void mma_f16(uint32_t c[2], const uint32_t a[4],
                                               uint32_t b0, uint32_t b1) {
    asm volatile("mma.sync.aligned.m16n8k16.row.col.f16.f16.f16.f16 "
                 "{%0,%1}, {%2,%3,%4,%5}, {%6,%7}, {%0,%1};"
                 : "+r"(c[0]), "+r"(c[1])
                 : "r"(a[0]), "r"(a[1]), "r"(a[2]), "r"(a[3]), "r"(b0), "r"(b1));
}
static __device__ __forceinline__ void bulk_ld(uint32_t dst, const void* src,
                                               uint32_t bytes, uint32_t mbar) {
    asm volatile("cp.async.bulk.shared::cluster.global.mbarrier::complete_tx::bytes "
                 "[%0], [%1], %2, [%3];"
                 :: "r"(dst), "l"(src), "r"(bytes), "r"(mbar) : "memory");
}
#define MBARRIER_INIT(addr, cnt) \
    asm volatile("mbarrier.init.shared.b64 [%0], %1;" :: "r"((uint32_t)(addr)), "r"((uint32_t)(cnt)) : "memory")
#define MBARRIER_EXPECT_TX(addr, bytes) \
    asm volatile("mbarrier.arrive.expect_tx.shared.b64 _, [%0], %1;" :: "r"((uint32_t)(addr)), "r"((uint32_t)(bytes)) : "memory")
#define MBARRIER_WAIT_PARITY(mbar_addr, parity) do { \
    uint32_t _mbar = (uint32_t)(mbar_addr); \
    uint32_t _par = (uint32_t)(parity); \
    uint32_t _done; \
    asm volatile("{\n\t.reg .pred p;\n\t" \
        "mbarrier.try_wait.parity.acquire.cta.shared::cta.b64 p, [%1], %2;\n\t" \
        "selp.b32 %0, 1, 0, p;\n\t}" : "=r"(_done) : "r"(_mbar), "r"(_par) : "memory"); \
    if (!_done) { \
        asm volatile("{\n\t.reg .pred P1;\n\t" \
            "WAIT_LOOP_%=:\n\t" \
            "mbarrier.try_wait.parity.acquire.cta.shared::cta.b64 P1, [%0], %1, 0x989680;\n\t" \
            "@P1 bra.uni WAIT_DONE_%=;\n\t" \
            "bra.uni WAIT_LOOP_%=;\n\t" \
            "WAIT_DONE_%=:\n\t}" :: "r"(_mbar), "r"(_par) : "memory"); \
    } \
} while (0)

// swizzled byte offset inside a [rows x 256B] f16 tile (16B chunks, XOR by row)
static __device__ __forceinline__ uint32_t tile_off(int r, int chunk) {
    return (uint32_t)(r * 256 + ((chunk ^ (r & 7)) << 4));
}

// ---------------- Kernel A: normalize + f16 convert into flat tiles ---------
__global__ void prep_kernel(const float* __restrict__ q, const float* __restrict__ u) {
    int row  = blockIdx.x * (blockDim.x >> 5) + (threadIdx.x >> 5);
    int lane = threadIdx.x & 31;
    int total = NU + BQ + PADROWS;
    if (row >= total) return;

    if (row >= NU + BQ) {
        int r = 32 + (row - (NU + BQ));
        size_t tbase = (size_t)(NT_FLAT - 1) << 13;
        uint32_t off = tile_off(r, lane >> 1) >> 2;
        g_ubsw[tbase + off + (lane & 1) * 2]     = 0u;
        g_ubsw[tbase + off + (lane & 1) * 2 + 1] = 0u;
        return;
    }

    const float* src;
    if (row < NU) src = u + (size_t)row * DIM;
    else          src = q + (size_t)(row - NU) * DIM;
    float4 v = *(const float4*)(src + lane * 4);
    float s = v.x * v.x + v.y * v.y + v.z * v.z + v.w * v.w;
    #pragma unroll
    for (int o = 16; o > 0; o >>= 1) s += __shfl_xor_sync(0xffffffffu, s, o);
    float inv = 1.0f / fmaxf(sqrtf(s), 1e-12f);
    float4 o4 = make_float4(v.x * inv, v.y * inv, v.z * inv, v.w * inv);

    __half2 h0 = __floats2half2_rn(o4.x, o4.y);
    __half2 h1 = __floats2half2_rn(o4.z, o4.w);
    uint32_t f0 = *(uint32_t*)&h0, f1 = *(uint32_t*)&h1;

    if (row < NU) {
        *(float4*)(g_ue_n + (size_t)row * DIM + lane * 4) = o4;
        int tile = row >> 7, n = row & 127;
        size_t tbase = (size_t)tile << 13;
        uint32_t off = tile_off(n, lane >> 1) >> 2;
        g_ubsw[tbase + off + (lane & 1) * 2]     = f0;
        g_ubsw[tbase + off + (lane & 1) * 2 + 1] = f1;
    } else {
        int r = row - NU;
        *(float4*)(g_q_n + (size_t)r * DIM + lane * 4) = o4;
        uint2 pk = make_uint2(f0, f1);
        *(uint2*)(g_qh + (size_t)r * DIM + lane * 4) = pk;
    }
}

// ---------------- Kernel B: f16 HMMA sims, 64x64 warp tiles -----------------
// grid (16 qb, 9 chunks), 256 threads (8 warps, 4x2 warp grid)
// SMEM lists: per-row top-8 (value,index) live in smem; warp-cooperative scan.
#define OFF_A    0                                   // 65536
#define OFF_B0   65536
#define OFF_B1   98304
#define OFF_SIMS 131072                              // 256 * 65 * 4 = 66560
#define OFF_LV   (OFF_SIMS + 256 * SP_U32 * 4)       // 197632, 8192B
#define OFF_LI   (OFF_LV + 8192)                     // 205824, 8192B
#define OFF_TRIG (OFF_LI + 8192)                     // 214016, 512B (uchar[256][2])
#define OFF_MBAR (OFF_TRIG + 512)                    // 214528
#define SMEM_BYTES (OFF_MBAR + 64 + 1024)

__global__ __launch_bounds__(256) void cand_kernel() {
    extern __shared__ char sraw[];
    uint32_t sb0 = smem_u32(sraw);
    uint32_t ab = (sb0 + 1023) & ~1023u;
    char* base = sraw + (ab - sb0);

    uint32_t* simsu = (uint32_t*)(base + OFF_SIMS);
    float*    lv    = (float*)(base + OFF_LV);
    int*      li    = (int*)(base + OFF_LI);
    uchar*    trig8 = (uchar*)(base + OFF_TRIG);
    const uint32_t MB = ab + OFF_MBAR;

    const int t = threadIdx.x;
    const int w = t >> 5, lane = t & 31;
    const int wr = w >> 1, wc = w & 1;     // 4x2 warp grid, 64x64 tiles
    const int m0w = wr * 64;
    const int n0w = wc * 64;
    const int q0 = blockIdx.x * TM;
    const int ck = blockIdx.y;
    const int t0 = (ck * NT_FLAT) / NCHUNK;
    const int t1 = ((ck + 1) * NT_FLAT) / NCHUNK;
    const int ntile = t1 - t0;

    if (t == 0) { MBARRIER_INIT(MB, 1); MBARRIER_INIT(MB + 8, 1); }
    for (int i = t; i < TM * CAND; i += 256) { lv[i] = NEG_INF; li[i] = 0; }
    for (int i = t; i < TM * 2; i += 256) trig8[i] = 0;

    // build swizzled query tile (256 rows)
    {
        const uint4* src = (const uint4*)(g_qh + (size_t)q0 * DIM);
        for (int i = t; i < TM * 16; i += 256) {
            int r = i >> 4, c = i & 15;
            *(uint4*)(base + OFF_A + tile_off(r, c)) = src[i];
        }
    }
    __syncthreads();

    const uint32_t A_s = ab + OFF_A;
    const uint32_t Bs_[2] = { ab + OFF_B0, ab + OFF_B1 };
    const char* tb = (const char*)g_ubsw;

    if (t == 0) {
        MBARRIER_EXPECT_TX(MB,     32768u); bulk_ld(Bs_[0], tb + ((size_t)t0 << 15),       32768u, MB);
        MBARRIER_EXPECT_TX(MB + 8, 32768u); bulk_ld(Bs_[1], tb + ((size_t)(t0 + 1) << 15), 32768u, MB + 8);
    }

    const int a_row0 = m0w + (lane & 15);
    const int b_row0 = n0w + (lane & 7) + ((lane >> 4) << 3);
    const int a_chsel = (lane >> 4);
    const int b_chsel = ((lane >> 3) & 1);

    int ph[2] = {0, 0};
    for (int i = 0; i < ntile; i++) {
        const int s = i & 1;
        const uint32_t Bs = Bs_[s];
        const int g = t0 + i;
        MBARRIER_WAIT_PARITY(MB + s * 8, ph[s]); ph[s] ^= 1;

        // ---- MMA: warp tile 64 rows x 64 cols, f16 accum ----
        uint32_t acc[4][8][2];
        #pragma unroll
        for (int mi = 0; mi < 4; mi++)
            #pragma unroll
            for (int nf = 0; nf < 8; nf++) { acc[mi][nf][0] = 0u; acc[mi][nf][1] = 0u; }

        #pragma unroll
        for (int k = 0; k < 8; k++) {
            uint32_t af[4][4], bf[4][4];
            #pragma unroll
            for (int mi = 0; mi < 4; mi++)
                ldsm_x4(A_s + tile_off(a_row0 + mi * 16, 2 * k + a_chsel), af[mi]);
            #pragma unroll
            for (int gg = 0; gg < 4; gg++)
                ldsm_x4(Bs + tile_off(b_row0 + gg * 16, 2 * k + b_chsel), bf[gg]);
            #pragma unroll
            for (int gg = 0; gg < 4; gg++)
                #pragma unroll
                for (int mi = 0; mi < 4; mi++) {
                    mma_f16(acc[mi][gg * 2 + 0], af[mi], bf[gg][0], bf[gg][1]);
                    mma_f16(acc[mi][gg * 2 + 1], af[mi], bf[gg][2], bf[gg][3]);
                }
        }

        // ---- per-(row, own-half) max vs smem list tail; spill own half ----
        // Exact: if this half's max < tail, no candidate lives in this half.
        #pragma unroll
        for (int mi = 0; mi < 4; mi++)
            #pragma unroll
            for (int h = 0; h < 2; h++) {
                __half2 m2 = *(__half2*)&acc[mi][0][h];
                #pragma unroll
                for (int nf = 1; nf < 8; nf++)
                    m2 = __hmax2(m2, *(__half2*)&acc[mi][nf][h]);
                float mx = fmaxf(__low2float(m2), __high2float(m2));
                mx = fmaxf(mx, __shfl_xor_sync(0xffffffffu, mx, 1));
                mx = fmaxf(mx, __shfl_xor_sync(0xffffffffu, mx, 2));
                int row = m0w + mi * 16 + (lane >> 2) + h * 8;
                float tail = lv[row * CAND + (CAND - 1)];   // stale-safe (only grows)
                if (mx >= tail) {
                    if ((lane & 3) == 0) trig8[row * 2 + wc] = 1;
                    #pragma unroll
                    for (int nf = 0; nf < 8; nf++)
                        simsu[row * SP_U32 + wc * 32 + nf * 4 + (lane & 3)] = acc[mi][nf][h];
                }
            }
        __syncthreads();   // spills + flags visible; B[s] fully consumed

        if (t == 0 && i + 2 < ntile) {
            MBARRIER_EXPECT_TX(MB + s * 8, 32768u);
            bulk_ld(Bs, tb + ((size_t)(g + 2) << 15), 32768u, MB + s * 8);
        }

        // ---- warp-cooperative scan: warp w owns rows [w*32, w*32+32) ----
        {
            int r = w * 32 + lane;
            unsigned short tr = *(unsigned short*)&trig8[r * 2];
            unsigned bal = __ballot_sync(0xffffffffu, tr != 0);
            const int cbase = g * TN;
            while (bal) {
                int src = __ffs(bal) - 1; bal &= bal - 1;
                int rr = w * 32 + src;
                unsigned trr = __shfl_sync(0xffffffffu, (unsigned)tr, src);
                #pragma unroll
                for (int h = 0; h < 2; h++) {
                    if (!(trr & (h ? 0xff00u : 0x00ffu))) continue;
                    uint32_t pk = simsu[rr * SP_U32 + h * 32 + lane];
                    __half2 hv = *(__half2*)&pk;
                    float v0 = __low2float(hv), v1 = __high2float(hv);
                    float tailv = lv[rr * CAND + (CAND - 1)];
                    int   taili = li[rr * CAND + (CAND - 1)];
                    int gcol = cbase + h * 64 + lane * 2;
                    bool c0 = (gcol < NU) &&
                              (v0 > tailv || (v0 == tailv && gcol < taili));
                    bool c1 = (gcol + 1 < NU) &&
                              (v1 > tailv || (v1 == tailv && gcol + 1 < taili));
                    unsigned hb = __ballot_sync(0xffffffffu, c0 || c1);
                    while (hb) {
                        int hl = __ffs(hb) - 1; hb &= hb - 1;
                        float w0 = __shfl_sync(0xffffffffu, v0, hl);
                        float w1 = __shfl_sync(0xffffffffu, v1, hl);
                        int   fl = __shfl_sync(0xffffffffu, (int)c0 | ((int)c1 << 1), hl);
                        if (lane == 0) {
                            int gc = cbase + h * 64 + hl * 2;
                            float* L = lv + rr * CAND;
                            int*   I = li + rr * CAND;
                            #pragma unroll
                            for (int e2 = 0; e2 < 2; e2++) {
                                if (!(fl & (1 << e2))) continue;
                                float vv = e2 ? w1 : w0;
                                int   ii = gc + e2;
                                // re-verify against CURRENT tail (exact)
                                if (vv > L[CAND - 1] ||
                                    (vv == L[CAND - 1] && ii < I[CAND - 1])) {
                                    int j = CAND - 1;
                                    while (j > 0 && (vv > L[j - 1] ||
                                           (vv == L[j - 1] && ii < I[j - 1]))) {
                                        L[j] = L[j - 1]; I[j] = I[j - 1]; j--;
                                    }
                                    L[j] = vv; I[j] = ii;
                                }
                            }
                        }
                    }
                }
                if (lane == 0) *(unsigned short*)&trig8[rr * 2] = 0;
            }
        }
        __syncthreads();   // lists/flags settled before next tile's spill
    }

    // emit candidate indices (thread t owns query row q0+t)
    {
        size_t b = (size_t)(q0 + t) * NCAND + ck * CAND;
        #pragma unroll
        for (int e = 0; e < CAND; e++) g_ci[b + e] = li[t * CAND + e];
    }
}

// ---------------- Kernel C: exact rescore + select + gather -----------------
__global__ void finalize_kernel(float* __restrict__ out) {
    __shared__ float cv[NCAND];
    __shared__ int   ci[NCAND];
    __shared__ int   sel[TOPK];
    __shared__ float selv[TOPK];

    const int q = blockIdx.x;
    const int t = threadIdx.x;
    const int w = t >> 5, lane = t & 31;

    if (t < NCAND) ci[t] = g_ci[(size_t)q * NCAND + t];
    __syncthreads();

    // exact fp32 rescore: warp w handles 18 candidates
    float4 qv = *(const float4*)(g_q_n + (size_t)q * DIM + lane * 4);
    #pragma unroll 1
    for (int cc = 0; cc < 18; cc++) {
        int slot = w * 18 + cc;
        int idx = ci[slot];
        float4 uv = *(const float4*)(g_ue_n + (size_t)idx * DIM + lane * 4);
        float s = qv.x * uv.x;
        s = fmaf(qv.y, uv.y, s);
        s = fmaf(qv.z, uv.z, s);
        s = fmaf(qv.w, uv.w, s);
        #pragma unroll
        for (int o = 16; o > 0; o >>= 1) s += __shfl_xor_sync(0xffffffffu, s, o);
        if (lane == 0) cv[slot] = s;
    }
    __syncthreads();

    if (t == 0) {
        float bv[K1]; int bi[K1]; int cnt = 0;
        for (int i = 0; i < NCAND; i++) {
            float v = cv[i]; int id = ci[i];
            bool better = (cnt < K1) || (v > bv[K1 - 1]) || (v == bv[K1 - 1] && id < bi[K1 - 1]);
            if (!better) continue;
            int j = (cnt < K1) ? cnt : K1 - 1;
            while (j > 0 && (v > bv[j - 1] || (v == bv[j - 1] && id < bi[j - 1]))) {
                bv[j] = bv[j - 1]; bi[j] = bi[j - 1]; j--;
            }
            bv[j] = v; bi[j] = id;
            if (cnt < K1) cnt++;
        }
        int order[K1]; int nv = 0;
        for (int i = 0; i < K1; i++) if (bv[i] < 0.9999f) order[nv++] = i;
        int oi = nv;
        for (int i = 0; i < K1; i++) if (!(bv[i] < 0.9999f)) order[oi++] = i;
        for (int j = 0; j < TOPK; j++) {
            int pos = (nv > 0) ? order[min(j, nv - 1)] : j;
            sel[j] = bi[pos]; selv[j] = bv[pos];
        }
    }
    __syncthreads();

    float* oute = out;                              // [BQ, TOPK, DIM]
    float* outs = out + (size_t)BQ * TOPK * DIM;    // [BQ, TOPK]
    #pragma unroll
    for (int j = 0; j < TOPK; j++)
        oute[((size_t)q * TOPK + j) * DIM + t] = g_ue_n[(size_t)sel[j] * DIM + t];
    if (t < TOPK) outs[(size_t)q * TOPK + t] = selv[t];
}

// ---------------- launch ----------------------------------------------------
extern "C" void kernel_launch(void* const* d_in, const int* in_sizes, int n_in,
                              void* d_out, int out_size) {
    const float* q = (const float*)d_in[0];
    const float* u = (const float*)d_in[1];
    if (n_in >= 2 && in_sizes[0] != BQ * DIM) { const float* tmp = q; q = u; u = tmp; }
    float* out = (float*)d_out;

    int rows = NU + BQ + PADROWS;
    prep_kernel<<<(rows + 7) / 8, 256>>>(q, u);

    cudaFuncSetAttribute(cand_kernel, cudaFuncAttributeMaxDynamicSharedMemorySize, SMEM_BYTES);
    cand_kernel<<<dim3(QB, NCHUNK), 256, SMEM_BYTES>>>();

    finalize_kernel<<<BQ, DIM>>>(out);
}

// round 16
// speedup vs baseline: 1.0825x; 1.0825x over previous
#include <cuda_runtime.h>
#include <cuda_fp16.h>
#include <math.h>
#include <cstdint>

// ---------------- problem constants ----------------
#define BQ   4096
#define NU   100000
#define DIM  128
#define TOPK 5
#define K1   6
#define TM   256                       // queries per CTA
#define TN   128                       // users per tile
#define QB   (BQ / TM)                 // 16
#define NCHUNK 9                       // user-range chunks -> 144 CTAs
#define NT_FLAT 782                    // ceil(100000/128); last tile: 32 valid + 96 pad
#define PADROWS 96
#define CAND 8
#define NCAND (NCHUNK * CAND)          // 72
#define SP_U32 65                      // half2-spill pitch in u32
#define NEG_INF (-3.402823466e38f)

// ---------------- device scratch -------------------------------------------
__device__ float    g_ue_n[(size_t)NU * DIM];
__device__ float    g_q_n[(size_t)BQ * DIM];
__device__ uint32_t g_ubsw[(size_t)NT_FLAT * 8192];   // flat pre-swizzled f16 tiles (32KB each)
__device__ __half   g_qh[(size_t)BQ * DIM];
__device__ int      g_ci[(size_t)BQ * NCAND];

// ---------------- helpers ---------------------------------------------------
static __device__ __forceinline__ uint32_t smem_u32(const void* p) {
    uint32_t a;
    asm("{ .reg .u64 t; cvta.to.shared.u64 t, %1; cvt.u32.u64 %0, t; }" : "=r"(a) : "l"(p));
    return a;
}
static __device__ __forceinline__ void ldsm_x4(uint32_t addr, uint32_t r[4]) {
    asm volatile("ldmatrix.sync.aligned.m8n8.x4.shared.b16 {%0,%1,%2,%3}, [%4];"
                 : "=r"(r[0]), "=r"(r[1]), "=r"(r[2]), "=r"(r[3]) : "r"(addr));
}
static __device__ __forceinline__ void mma_f16(uint32_t c[2], const uint32_t a[4],
                                               uint32_t b0, uint32_t b1) {
    asm volatile("mma.sync.aligned.m16n8k16.row.col.f16.f16.f16.f16 "
                 "{%0,%1}, {%2,%3,%4,%5}, {%6,%7}, {%0,%1};"
                 : "+r"(c[0]), "+r"(c[1])
                 : "r"(a[0]), "r"(a[1]), "r"(a[2]), "r"(a[3]), "r"(b0), "r"(b1));
}
static __device__ __forceinline__ void bulk_ld(uint32_t dst, const void* src,
                                               uint32_t bytes, uint32_t mbar) {
    asm volatile("cp.async.bulk.shared::cluster.global.mbarrier::complete_tx::bytes "
                 "[%0], [%1], %2, [%3];"
                 :: "r"(dst), "l"(src), "r"(bytes), "r"(mbar) : "memory");
}
#define MBARRIER_INIT(addr, cnt) \
    asm volatile("mbarrier.init.shared.b64 [%0], %1;" :: "r"((uint32_t)(addr)), "r"((uint32_t)(cnt)) : "memory")
#define MBARRIER_EXPECT_TX(addr, bytes) \
    asm volatile("mbarrier.arrive.expect_tx.shared.b64 _, [%0], %1;" :: "r"((uint32_t)(addr)), "r"((uint32_t)(bytes)) : "memory")
#define MBARRIER_WAIT_PARITY(mbar_addr, parity) do { \
    uint32_t _mbar = (uint32_t)(mbar_addr); \
    uint32_t _par = (uint32_t)(parity); \
    uint32_t _done; \
    asm volatile("{\n\t.reg .pred p;\n\t" \
        "mbarrier.try_wait.parity.acquire.cta.shared::cta.b64 p, [%1], %2;\n\t" \
        "selp.b32 %0, 1, 0, p;\n\t}" : "=r"(_done) : "r"(_mbar), "r"(_par) : "memory"); \
    if (!_done) { \
        asm volatile("{\n\t.reg .pred P1;\n\t" \
            "WAIT_LOOP_%=:\n\t" \
            "mbarrier.try_wait.parity.acquire.cta.shared::cta.b64 P1, [%0], %1, 0x989680;\n\t" \
            "@P1 bra.uni WAIT_DONE_%=;\n\t" \
            "bra.uni WAIT_LOOP_%=;\n\t" \
            "WAIT_DONE_%=:\n\t}" :: "r"(_mbar), "r"(_par) : "memory"); \
    } \
} while (0)

// swizzled byte offset inside a [rows x 256B] f16 tile (16B chunks, XOR by row)
static __device__ __forceinline__ uint32_t tile_off(int r, int chunk) {
    return (uint32_t)(r * 256 + ((chunk ^ (r & 7)) << 4));
}

// ---------------- Kernel A: normalize + f16 convert into flat tiles ---------
__global__ void prep_kernel(const float* __restrict__ q, const float* __restrict__ u) {
    int row  = blockIdx.x * (blockDim.x >> 5) + (threadIdx.x >> 5);
    int lane = threadIdx.x & 31;
    int total = NU + BQ + PADROWS;
    if (row >= total) return;

    if (row >= NU + BQ) {
        int r = 32 + (row - (NU + BQ));
        size_t tbase = (size_t)(NT_FLAT - 1) << 13;
        uint32_t off = tile_off(r, lane >> 1) >> 2;
        g_ubsw[tbase + off + (lane & 1) * 2]     = 0u;
        g_ubsw[tbase + off + (lane & 1) * 2 + 1] = 0u;
        return;
    }

    const float* src;
    if (row < NU) src = u + (size_t)row * DIM;
    else          src = q + (size_t)(row - NU) * DIM;
    float4 v = *(const float4*)(src + lane * 4);
    float s = v.x * v.x + v.y * v.y + v.z * v.z + v.w * v.w;
    #pragma unroll
    for (int o = 16; o > 0; o >>= 1) s += __shfl_xor_sync(0xffffffffu, s, o);
    float inv = 1.0f / fmaxf(sqrtf(s), 1e-12f);
    float4 o4 = make_float4(v.x * inv, v.y * inv, v.z * inv, v.w * inv);

    __half2 h0 = __floats2half2_rn(o4.x, o4.y);
    __half2 h1 = __floats2half2_rn(o4.z, o4.w);
    uint32_t f0 = *(uint32_t*)&h0, f1 = *(uint32_t*)&h1;

    if (row < NU) {
        *(float4*)(g_ue_n + (size_t)row * DIM + lane * 4) = o4;
        int tile = row >> 7, n = row & 127;
        size_t tbase = (size_t)tile << 13;
        uint32_t off = tile_off(n, lane >> 1) >> 2;
        g_ubsw[tbase + off + (lane & 1) * 2]     = f0;
        g_ubsw[tbase + off + (lane & 1) * 2 + 1] = f1;
    } else {
        int r = row - NU;
        *(float4*)(g_q_n + (size_t)r * DIM + lane * 4) = o4;
        uint2 pk = make_uint2(f0, f1);
        *(uint2*)(g_qh + (size_t)r * DIM + lane * 4) = pk;
    }
}

// ---------------- Kernel B: f16 HMMA sims, 64x64 warp tiles -----------------
// grid (16 qb, 9 chunks), 256 threads (8 warps, 4x2 warp grid)
// R14 structure + per-half trigger flags (spill/scan only the flagged half)
#define OFF_A    0                                   // 65536
#define OFF_B0   65536
#define OFF_B1   98304
#define OFF_SIMS 131072                              // 256 * 65 * 4 = 66560
#define OFF_THR  (OFF_SIMS + 256 * SP_U32 * 4)       // 197632, 1024B
#define OFF_TRIG (OFF_THR + 1024)                    // 198656, int[256][2] = 2048B
#define OFF_MBAR (OFF_TRIG + 2048)                   // 200704
#define SMEM_BYTES (OFF_MBAR + 64 + 1024)

__global__ __launch_bounds__(256) void cand_kernel() {
    extern __shared__ char sraw[];
    uint32_t sb0 = smem_u32(sraw);
    uint32_t ab = (sb0 + 1023) & ~1023u;
    char* base = sraw + (ab - sb0);

    uint32_t* simsu = (uint32_t*)(base + OFF_SIMS);
    float*    thr   = (float*)(base + OFF_THR);
    int*      trig  = (int*)(base + OFF_TRIG);    // [row][half]
    const uint32_t MB = ab + OFF_MBAR;

    const int t = threadIdx.x;
    const int w = t >> 5, lane = t & 31;
    const int wr = w >> 1, wc = w & 1;     // 4x2 warp grid, 64x64 tiles
    const int m0w = wr * 64;
    const int n0w = wc * 64;
    const int q0 = blockIdx.x * TM;
    const int ck = blockIdx.y;
    const int t0 = (ck * NT_FLAT) / NCHUNK;
    const int t1 = ((ck + 1) * NT_FLAT) / NCHUNK;
    const int ntile = t1 - t0;

    float topv[CAND]; int topi[CAND];
    #pragma unroll
    for (int p = 0; p < CAND; p++) { topv[p] = NEG_INF; topi[p] = 0; }

    if (t == 0) { MBARRIER_INIT(MB, 1); MBARRIER_INIT(MB + 8, 1); }
    for (int i = t; i < TM; i += 256) thr[i] = NEG_INF;
    for (int i = t; i < TM * 2; i += 256) trig[i] = 0;

    // build swizzled query tile (256 rows)
    {
        const uint4* src = (const uint4*)(g_qh + (size_t)q0 * DIM);
        for (int i = t; i < TM * 16; i += 256) {
            int r = i >> 4, c = i & 15;
            *(uint4*)(base + OFF_A + tile_off(r, c)) = src[i];
        }
    }
    __syncthreads();

    const uint32_t A_s = ab + OFF_A;
    const uint32_t Bs_[2] = { ab + OFF_B0, ab + OFF_B1 };
    const char* tb = (const char*)g_ubsw;

    if (t == 0) {
        MBARRIER_EXPECT_TX(MB,     32768u); bulk_ld(Bs_[0], tb + ((size_t)t0 << 15),       32768u, MB);
        MBARRIER_EXPECT_TX(MB + 8, 32768u); bulk_ld(Bs_[1], tb + ((size_t)(t0 + 1) << 15), 32768u, MB + 8);
    }

    const int a_row0 = m0w + (lane & 15);
    const int b_row0 = n0w + (lane & 7) + ((lane >> 4) << 3);
    const int a_chsel = (lane >> 4);
    const int b_chsel = ((lane >> 3) & 1);

    int ph[2] = {0, 0};
    for (int i = 0; i < ntile; i++) {
        const int s = i & 1;
        const uint32_t Bs = Bs_[s];
        const int g = t0 + i;
        MBARRIER_WAIT_PARITY(MB + s * 8, ph[s]); ph[s] ^= 1;

        // ---- MMA: warp tile 64 rows x 64 cols, f16 accum ----
        uint32_t acc[4][8][2];
        #pragma unroll
        for (int mi = 0; mi < 4; mi++)
            #pragma unroll
            for (int nf = 0; nf < 8; nf++) { acc[mi][nf][0] = 0u; acc[mi][nf][1] = 0u; }

        #pragma unroll
        for (int k = 0; k < 8; k++) {
            uint32_t af[4][4], bf[4][4];
            #pragma unroll
            for (int mi = 0; mi < 4; mi++)
                ldsm_x4(A_s + tile_off(a_row0 + mi * 16, 2 * k + a_chsel), af[mi]);
            #pragma unroll
            for (int gg = 0; gg < 4; gg++)
                ldsm_x4(Bs + tile_off(b_row0 + gg * 16, 2 * k + b_chsel), bf[gg]);
            #pragma unroll
            for (int gg = 0; gg < 4; gg++)
                #pragma unroll
                for (int mi = 0; mi < 4; mi++) {
                    mma_f16(acc[mi][gg * 2 + 0], af[mi], bf[gg][0], bf[gg][1]);
                    mma_f16(acc[mi][gg * 2 + 1], af[mi], bf[gg][2], bf[gg][3]);
                }
        }

        // ---- per-(row, own-half) max + threshold trig (strict >) ----
        #pragma unroll
        for (int mi = 0; mi < 4; mi++)
            #pragma unroll
            for (int h = 0; h < 2; h++) {
                __half2 m2 = *(__half2*)&acc[mi][0][h];
                #pragma unroll
                for (int nf = 1; nf < 8; nf++)
                    m2 = __hmax2(m2, *(__half2*)&acc[mi][nf][h]);
                float mx = fmaxf(__low2float(m2), __high2float(m2));
                mx = fmaxf(mx, __shfl_xor_sync(0xffffffffu, mx, 1));
                mx = fmaxf(mx, __shfl_xor_sync(0xffffffffu, mx, 2));
                int row = m0w + mi * 16 + (lane >> 2) + h * 8;
                if ((lane & 3) == 0 && mx > thr[row]) trig[row * 2 + wc] = 1;
            }
        __syncthreads();   // trig visible; B[s] fully consumed

        // ---- spill only flagged (row, own-half) slices ----
        #pragma unroll
        for (int mi = 0; mi < 4; mi++) {
            int r0 = m0w + mi * 16 + (lane >> 2);
            #pragma unroll
            for (int h = 0; h < 2; h++) {
                int row = r0 + h * 8;
                if (trig[row * 2 + wc]) {
                    #pragma unroll
                    for (int nf = 0; nf < 8; nf++)
                        simsu[row * SP_U32 + wc * 32 + nf * 4 + (lane & 3)] = acc[mi][nf][h];
                }
            }
        }
        if (t == 0 && i + 2 < ntile) {
            MBARRIER_EXPECT_TX(MB + s * 8, 32768u);
            bulk_ld(Bs, tb + ((size_t)(g + 2) << 15), 32768u, MB + s * 8);
        }
        __syncthreads();   // sims visible

        // ---- owner thread t scans its row's flagged halves ----
        {
            int f0 = trig[t * 2 + 0], f1 = trig[t * 2 + 1];
            if (f0 | f1) {
                int nvalid = min(TN, NU - g * TN);
                const int cbase = g * TN;
                const uint32_t* srow = simsu + t * SP_U32;
                #pragma unroll 1
                for (int h = 0; h < 2; h++) {
                    if (!(h ? f1 : f0)) continue;
                    int c0 = h * 64;
                    int cend = min(64, nvalid - c0);
                    for (int cp = 0; cp * 2 < cend; cp++) {
                        uint32_t pk = srow[h * 32 + cp];
                        __half2 hv = *(__half2*)&pk;
                        #pragma unroll
                        for (int hh = 0; hh < 2; hh++) {
                            int col = c0 + cp * 2 + hh;
                            if (col >= nvalid) break;
                            float v = hh ? __high2float(hv) : __low2float(hv);
                            int idx = cbase + col;
                            if (v > topv[CAND - 1] ||
                                (v == topv[CAND - 1] && idx < topi[CAND - 1])) {
                                float vv = v; int ii = idx;
                                #pragma unroll
                                for (int p = 0; p < CAND; p++) {
                                    bool better = (vv > topv[p]) ||
                                                  (vv == topv[p] && ii < topi[p]);
                                    if (better) {
                                        float tv = topv[p]; topv[p] = vv; vv = tv;
                                        int   ti = topi[p]; topi[p] = ii; ii = ti;
                                    }
                                }
                            }
                        }
                    }
                }
                thr[t] = topv[CAND - 1];
                trig[t * 2 + 0] = 0;
                trig[t * 2 + 1] = 0;
            }
        }
        __syncthreads();
    }

    {
        size_t b = (size_t)(q0 + t) * NCAND + ck * CAND;
        #pragma unroll
        for (int e = 0; e < CAND; e++) g_ci[b + e] = topi[e];
    }
}

// ---------------- Kernel C: exact rescore + select + gather -----------------
__global__ void finalize_kernel(float* __restrict__ out) {
    __shared__ float cv[NCAND];
    __shared__ int   ci[NCAND];
    __shared__ int   sel[TOPK];
    __shared__ float selv[TOPK];

    const int q = blockIdx.x;
    const int t = threadIdx.x;
    const int w = t >> 5, lane = t & 31;

    if (t < NCAND) ci[t] = g_ci[(size_t)q * NCAND + t];
    __syncthreads();

    // exact fp32 rescore: warp w handles 18 candidates
    float4 qv = *(const float4*)(g_q_n + (size_t)q * DIM + lane * 4);
    #pragma unroll 1
    for (int cc = 0; cc < 18; cc++) {
        int slot = w * 18 + cc;
        int idx = ci[slot];
        float4 uv = *(const float4*)(g_ue_n + (size_t)idx * DIM + lane * 4);
        float s = qv.x * uv.x;
        s = fmaf(qv.y, uv.y, s);
        s = fmaf(qv.z, uv.z, s);
        s = fmaf(qv.w, uv.w, s);
        #pragma unroll
        for (int o = 16; o > 0; o >>= 1) s += __shfl_xor_sync(0xffffffffu, s, o);
        if (lane == 0) cv[slot] = s;
    }
    __syncthreads();

    if (t == 0) {
        float bv[K1]; int bi[K1]; int cnt = 0;
        for (int i = 0; i < NCAND; i++) {
            float v = cv[i]; int id = ci[i];
            bool better = (cnt < K1) || (v > bv[K1 - 1]) || (v == bv[K1 - 1] && id < bi[K1 - 1]);
            if (!better) continue;
            int j = (cnt < K1) ? cnt : K1 - 1;
            while (j > 0 && (v > bv[j - 1] || (v == bv[j - 1] && id < bi[j - 1]))) {
                bv[j] = bv[j - 1]; bi[j] = bi[j - 1]; j--;
            }
            bv[j] = v; bi[j] = id;
            if (cnt < K1) cnt++;
        }
        int order[K1]; int nv = 0;
        for (int i = 0; i < K1; i++) if (bv[i] < 0.9999f) order[nv++] = i;
        int oi = nv;
        for (int i = 0; i < K1; i++) if (!(bv[i] < 0.9999f)) order[oi++] = i;
        for (int j = 0; j < TOPK; j++) {
            int pos = (nv > 0) ? order[min(j, nv - 1)] : j;
            sel[j] = bi[pos]; selv[j] = bv[pos];
        }
    }
    __syncthreads();

    float* oute = out;                              // [BQ, TOPK, DIM]
    float* outs = out + (size_t)BQ * TOPK * DIM;    // [BQ, TOPK]
    #pragma unroll
    for (int j = 0; j < TOPK; j++)
        oute[((size_t)q * TOPK + j) * DIM + t] = g_ue_n[(size_t)sel[j] * DIM + t];
    if (t < TOPK) outs[(size_t)q * TOPK + t] = selv[t];
}

// ---------------- launch ----------------------------------------------------
extern "C" void kernel_launch(void* const* d_in, const int* in_sizes, int n_in,
                              void* d_out, int out_size) {
    const float* q = (const float*)d_in[0];
    const float* u = (const float*)d_in[1];
    if (n_in >= 2 && in_sizes[0] != BQ * DIM) { const float* tmp = q; q = u; u = tmp; }
    float* out = (float*)d_out;

    int rows = NU + BQ + PADROWS;
    prep_kernel<<<(rows + 7) / 8, 256>>>(q, u);

    cudaFuncSetAttribute(cand_kernel, cudaFuncAttributeMaxDynamicSharedMemorySize, SMEM_BYTES);
    cand_kernel<<<dim3(QB, NCHUNK), 256, SMEM_BYTES>>>();

    finalize_kernel<<<BQ, DIM>>>(out);
}